// round 15
// baseline (speedup 1.0000x reference)
#include <cuda_runtime.h>
#include <cuda_fp16.h>
#include <math_constants.h>
#include <cstdint>

// Problem constants
static constexpr int Bsz = 8192;
static constexpr int S   = 30;
static constexpr int D   = 512;
static constexpr int H   = 1024;
static constexpr int K   = 1536;   // 3*D

static constexpr int NSHARES       = 1024;  // 8 rows each
static constexpr int SHARES_PER_MB = 16;    // 16 shares = 128 rows = one m-block

// Scratch (no device allocs allowed)
__device__ __align__(128) __half g_fh[(size_t)Bsz * K];
__device__ __align__(128) __half g_wh[(size_t)H * K];
__device__ int g_sync[65];   // [0] = ticket queue, [1+m] = m-block flags

// ---------------------------------------------------------------------------
// Helpers
// ---------------------------------------------------------------------------
__device__ __forceinline__ uint32_t smem_u32(const void* p) {
    uint32_t a;
    asm("{ .reg .u64 t; cvta.to.shared.u64 t, %1; cvt.u32.u64 %0, t; }" : "=r"(a) : "l"(p));
    return a;
}

__device__ __forceinline__ void cpa16(uint32_t s, const void* g) {
    asm volatile("cp.async.cg.shared.global [%0], [%1], 16;" :: "r"(s), "l"(g) : "memory");
}

__device__ __forceinline__ void ldsm4(uint32_t* r, uint32_t addr) {
    asm volatile("ldmatrix.sync.aligned.m8n8.x4.shared.b16 {%0,%1,%2,%3}, [%4];"
                 : "=r"(r[0]), "=r"(r[1]), "=r"(r[2]), "=r"(r[3]) : "r"(addr));
}

__device__ __forceinline__ void mma16816(float* d, const uint32_t* a, const uint32_t* b) {
    asm volatile(
        "mma.sync.aligned.m16n8k16.row.col.f32.f16.f16.f32 "
        "{%0,%1,%2,%3}, {%4,%5,%6,%7}, {%8,%9}, {%0,%1,%2,%3};"
        : "+f"(d[0]), "+f"(d[1]), "+f"(d[2]), "+f"(d[3])
        : "r"(a[0]), "r"(a[1]), "r"(a[2]), "r"(a[3]), "r"(b[0]), "r"(b[1]));
}

__device__ __forceinline__ uint32_t sw128(uint32_t off) {
    return off ^ ((off >> 3) & 0x70);
}

__device__ __forceinline__ void store_half4(__half* dst, float a, float b,
                                            float c, float d) {
    __half2 lo = __floats2half2_rn(a, b);
    __half2 hi = __floats2half2_rn(c, d);
    __half2* p = (__half2*)dst;
    p[0] = lo;
    p[1] = hi;
}

// ---------------------------------------------------------------------------
// W1 -> fp16
// ---------------------------------------------------------------------------
__global__ __launch_bounds__(256) void w1_cvt_kernel(
    const float* __restrict__ W1,
    __half* __restrict__ wh)
{
    int i = (blockIdx.x * 256 + threadIdx.x) * 4;
    float4 v = *(const float4*)&W1[i];
    store_half4(&wh[i], v.x, v.y, v.z, v.w);
}

// ---------------------------------------------------------------------------
// Feature share: 8 rows x 512 d, scalar with full register buffering —
// each thread issues all 30 s-loads up-front (needs the 128-reg budget;
// under an 80-reg cap ptxas sinks these loads and MLP collapses).
// ---------------------------------------------------------------------------
__device__ void do_share(
    int item, const float* __restrict__ emb, __half* __restrict__ fh,
    float wl0, float wl1, float wl2, float wm0, float wm1, float wm2, int tid)
{
#pragma unroll 1
    for (int i = 0; i < 16; ++i) {
        int idx = (i << 8) + tid;       // 0..4095
        int r   = idx >> 9;             // 0..7
        int d   = idx & 511;
        int row = (item << 3) + r;

        const float* p = emb + (size_t)row * (S * D) + d;

        float x[S];
#pragma unroll
        for (int s = 0; s < S; ++s) x[s] = p[s * D];

        float vl = -CUDART_INF_F;
        float vm = -CUDART_INF_F;
#pragma unroll
        for (int s = 0; s < 28; ++s) {
            float c = fmaf(x[s], wl0, fmaf(x[s + 1], wl1, x[s + 2] * wl2));
            vl = fmaxf(vl, c);
            if (s >= 23) {
                float cm = fmaf(x[s], wm0, fmaf(x[s + 1], wm1, x[s + 2] * wm2));
                vm = fmaxf(vm, cm);
            }
        }

        size_t base = (size_t)row * K;
        fh[base + d]         = __float2half_rn(vl);
        fh[base + D + d]     = __float2half_rn(vm);
        fh[base + 2 * D + d] = __float2half_rn(x[29]);
    }
}

// ---------------------------------------------------------------------------
// Fused kernel: ALL CTAs work-steal feature shares until their own m-block
// is published, then run the mma.sync GEMM. 2 CTAs/SM, full register budget.
// ---------------------------------------------------------------------------
#define GT 256
#define OFF_A 0
#define OFF_B 16384
#define STAGE 24576
#define NSTAGE 2
#define GEMM_SMEM (NSTAGE * STAGE)   // 48 KB

__device__ __forceinline__ void load_stage(
    uint32_t sbase, const __half* aG, const __half* bG, int k0, int tid)
{
#pragma unroll
    for (int o = tid; o < 1024; o += GT) {
        int r = o >> 3, c = o & 7;
        uint32_t sw = sw128((uint32_t)(r * 128 + c * 16));
        size_t g = (size_t)r * K + k0 + c * 8;
        cpa16(sbase + OFF_A + sw, aG + g);
    }
#pragma unroll
    for (int o = tid; o < 512; o += GT) {
        int r = o >> 3, c = o & 7;
        uint32_t sw = sw128((uint32_t)(r * 128 + c * 16));
        size_t g = (size_t)r * K + k0 + c * 8;
        cpa16(sbase + OFF_B + sw, bG + g);
    }
}

__global__ void __launch_bounds__(GT, 2) fused_kernel(
    const float* __restrict__ emb,
    const float* __restrict__ wl,
    const float* __restrict__ wm,
    const __half* __restrict__ wh,
    const float* __restrict__ W2,
    float* __restrict__ out)
{
    extern __shared__ char smem[];
    const uint32_t sb = smem_u32(smem);
    const int tid  = threadIdx.x;
    const int L    = blockIdx.x;     // 0..1023
    const int m    = L & 63;         // m-tile
    const int n0   = (L >> 6) * 64;  // n offset
    const int m0   = m * 128;

    __shared__ int s_item;

    // ---- Phase A: cooperative production (steal until own m-block done) ----
    {
        float wl0 = wl[0], wl1 = wl[1], wl2 = wl[2];
        float wm0 = wm[0], wm1 = wm[1], wm2 = wm[2];
        for (;;) {
            if (tid == 0) {
                if (*(volatile int*)&g_sync[1 + m] >= SHARES_PER_MB)
                    s_item = -1;                       // our tile is ready
                else
                    s_item = atomicAdd(&g_sync[0], 1); // steal a share
            }
            __syncthreads();
            int item = s_item;
            if (item < 0 || item >= NSHARES) break;
            do_share(item, emb, g_fh, wl0, wl1, wl2, wm0, wm1, wm2, tid);
            __syncthreads();   // all threads finished writing this share
            if (tid == 0) {
                __threadfence();
                atomicAdd(&g_sync[1 + (item >> 4)], 1);
            }
            __syncthreads();
        }
    }

    // ---- Gate: wait for this tile's 128 rows ----
    if (tid == 0) {
        while (*(volatile int*)&g_sync[1 + m] < SHARES_PER_MB)
            __nanosleep(200);
        __threadfence();
    }
    __syncthreads();

    // ---- Phase B: GEMM 128x64, 2-stage cp.async ----
    const int wid  = tid >> 5;
    const int lane = tid & 31;
    const int wmw  = wid & 3;
    const int wn   = wid >> 2;

    const __half* aG = g_fh + (size_t)m0 * K;
    const __half* bG = wh   + (size_t)n0 * K;

    float acc[2][4][4];
#pragma unroll
    for (int mt = 0; mt < 2; ++mt)
#pragma unroll
        for (int nt = 0; nt < 4; ++nt)
#pragma unroll
            for (int e = 0; e < 4; ++e) acc[mt][nt][e] = 0.f;

    const int aRow = (lane & 15);
    const int aKch = (lane >> 4);
    const int bRow = ((lane >> 4) << 3) + (lane & 7);
    const int bKch = (lane >> 3) & 1;

    load_stage(sb,         aG, bG, 0,  tid);
    asm volatile("cp.async.commit_group;" ::: "memory");
    load_stage(sb + STAGE, aG, bG, 64, tid);
    asm volatile("cp.async.commit_group;" ::: "memory");

    for (int c = 0; c < 24; ++c) {
        if (c < 23) asm volatile("cp.async.wait_group 1;" ::: "memory");
        else        asm volatile("cp.async.wait_group 0;" ::: "memory");
        __syncthreads();

        const uint32_t sbase = sb + (c & 1) * STAGE;

#pragma unroll
        for (int ks = 0; ks < 4; ++ks) {
            uint32_t ah[2][4], bh[2][4];
#pragma unroll
            for (int mt = 0; mt < 2; ++mt) {
                uint32_t off = (uint32_t)((wmw * 32 + mt * 16 + aRow) * 128
                                          + ks * 32 + aKch * 16);
                ldsm4(ah[mt], sbase + OFF_A + sw128(off));
            }
#pragma unroll
            for (int g = 0; g < 2; ++g) {
                uint32_t off = (uint32_t)((wn * 32 + g * 16 + bRow) * 128
                                          + ks * 32 + bKch * 16);
                ldsm4(bh[g], sbase + OFF_B + sw128(off));
            }
#pragma unroll
            for (int mt = 0; mt < 2; ++mt) {
#pragma unroll
                for (int nt = 0; nt < 4; ++nt) {
                    const uint32_t* bp = &bh[nt >> 1][(nt & 1) * 2];
                    mma16816(acc[mt][nt], ah[mt], bp);
                }
            }
        }

        __syncthreads();
        if (c + 2 < 24) {
            load_stage(sbase, aG, bG, (c + 2) * 64, tid);
            asm volatile("cp.async.commit_group;" ::: "memory");
        }
    }

    // Epilogue: tanh + W2 dot, quad reduce, atomicAdd per row.
    float w2v[4][2];
#pragma unroll
    for (int nt = 0; nt < 4; ++nt) {
        int col = n0 + wn * 32 + nt * 8 + 2 * (lane & 3);
        w2v[nt][0] = W2[col];
        w2v[nt][1] = W2[col + 1];
    }

#pragma unroll
    for (int mt = 0; mt < 2; ++mt) {
        float p0 = 0.f, p1 = 0.f;
#pragma unroll
        for (int nt = 0; nt < 4; ++nt) {
            p0 += tanhf(acc[mt][nt][0]) * w2v[nt][0]
                + tanhf(acc[mt][nt][1]) * w2v[nt][1];
            p1 += tanhf(acc[mt][nt][2]) * w2v[nt][0]
                + tanhf(acc[mt][nt][3]) * w2v[nt][1];
        }
        p0 += __shfl_xor_sync(0xFFFFFFFFu, p0, 1);
        p0 += __shfl_xor_sync(0xFFFFFFFFu, p0, 2);
        p1 += __shfl_xor_sync(0xFFFFFFFFu, p1, 1);
        p1 += __shfl_xor_sync(0xFFFFFFFFu, p1, 2);
        if ((lane & 3) == 0) {
            int r = m0 + wmw * 32 + mt * 16 + (lane >> 2);
            atomicAdd(&out[r], p0);
            atomicAdd(&out[r + 8], p1);
        }
    }
}

// ---------------------------------------------------------------------------
// Launch: single stream; counters reset per call (graph-replay safe).
// ---------------------------------------------------------------------------
extern "C" void kernel_launch(void* const* d_in, const int* in_sizes, int n_in,
                              void* d_out, int out_size)
{
    const float* emb    = (const float*)d_in[0];  // [8192, 30, 512]
    const float* w_long = (const float*)d_in[1];  // [3]
    const float* w_mid  = (const float*)d_in[2];  // [3]
    const float* W1     = (const float*)d_in[3];  // [1024, 1536]
    const float* W2     = (const float*)d_in[4];  // [1, 1024]
    float* out = (float*)d_out;                   // [8192]

    __half *wh;
    int* syncp;
    cudaGetSymbolAddress((void**)&wh, g_wh);
    cudaGetSymbolAddress((void**)&syncp, g_sync);

    static bool smem_set = false;
    if (!smem_set) {
        cudaFuncSetAttribute(fused_kernel,
                             cudaFuncAttributeMaxDynamicSharedMemorySize, GEMM_SMEM);
        smem_set = true;
    }

    cudaMemsetAsync(out, 0, (size_t)Bsz * sizeof(float));
    cudaMemsetAsync(syncp, 0, 65 * sizeof(int));

    w1_cvt_kernel<<<(H * K / 4) / 256, 256>>>(W1, wh);

    fused_kernel<<<1024, GT, GEMM_SMEM>>>(emb, w_long, w_mid, wh, W2, out);
}

// round 16
// speedup vs baseline: 1.2372x; 1.2372x over previous
#include <cuda_runtime.h>
#include <cuda_fp16.h>
#include <math_constants.h>
#include <cstdint>

// Problem constants
static constexpr int Bsz = 8192;
static constexpr int S   = 30;
static constexpr int D   = 512;
static constexpr int H   = 1024;
static constexpr int K   = 1536;   // 3*D

static constexpr int NCHUNK = 4;
static constexpr int BCH    = Bsz / NCHUNK;   // 2048 rows per pipeline chunk

// Scratch: fp16 features and fp16 W1 (no device allocs allowed)
__device__ __align__(128) __half g_fh[(size_t)Bsz * K];
__device__ __align__(128) __half g_wh[(size_t)H * K];

// ---------------------------------------------------------------------------
// Helpers
// ---------------------------------------------------------------------------
__device__ __forceinline__ uint32_t smem_u32(const void* p) {
    uint32_t a;
    asm("{ .reg .u64 t; cvta.to.shared.u64 t, %1; cvt.u32.u64 %0, t; }" : "=r"(a) : "l"(p));
    return a;
}

__device__ __forceinline__ void cpa16(uint32_t s, const void* g) {
    asm volatile("cp.async.cg.shared.global [%0], [%1], 16;" :: "r"(s), "l"(g) : "memory");
}

__device__ __forceinline__ void ldsm4(uint32_t* r, uint32_t addr) {
    asm volatile("ldmatrix.sync.aligned.m8n8.x4.shared.b16 {%0,%1,%2,%3}, [%4];"
                 : "=r"(r[0]), "=r"(r[1]), "=r"(r[2]), "=r"(r[3]) : "r"(addr));
}

__device__ __forceinline__ void mma16816(float* d, const uint32_t* a, const uint32_t* b) {
    asm volatile(
        "mma.sync.aligned.m16n8k16.row.col.f32.f16.f16.f32 "
        "{%0,%1,%2,%3}, {%4,%5,%6,%7}, {%8,%9}, {%0,%1,%2,%3};"
        : "+f"(d[0]), "+f"(d[1]), "+f"(d[2]), "+f"(d[3])
        : "r"(a[0]), "r"(a[1]), "r"(a[2]), "r"(a[3]), "r"(b[0]), "r"(b[1]));
}

__device__ __forceinline__ uint32_t sw128(uint32_t off) {
    return off ^ ((off >> 3) & 0x70);
}

__device__ __forceinline__ void store_half4(__half* dst, float a, float b,
                                            float c, float d) {
    __half2 lo = __floats2half2_rn(a, b);
    __half2 hi = __floats2half2_rn(c, d);
    __half2* p = (__half2*)dst;
    p[0] = lo;
    p[1] = hi;
}

// ---------------------------------------------------------------------------
// Kernel 1: feature extraction -> fp16 (per batch chunk; R7-proven scalar form)
// ---------------------------------------------------------------------------
__global__ __launch_bounds__(256) void feature_kernel(
    const float* __restrict__ emb,
    const float* __restrict__ wl,
    const float* __restrict__ wm,
    __half* __restrict__ fh)
{
    int t = blockIdx.x * blockDim.x + threadIdx.x;
    int b = t >> 9;
    int d = t & (D - 1);

    const float* p = emb + (size_t)b * (S * D) + d;

    float wl0 = wl[0], wl1 = wl[1], wl2 = wl[2];
    float wm0 = wm[0], wm1 = wm[1], wm2 = wm[2];

    float x0 = p[0];
    float x1 = p[D];
    float vl = -CUDART_INF_F;
    float vm = -CUDART_INF_F;

#pragma unroll
    for (int s = 0; s < 28; ++s) {
        float x2 = p[(s + 2) * D];
        float c = fmaf(x0, wl0, fmaf(x1, wl1, x2 * wl2));
        vl = fmaxf(vl, c);
        if (s >= 23) {
            float cm = fmaf(x0, wm0, fmaf(x1, wm1, x2 * wm2));
            vm = fmaxf(vm, cm);
        }
        x0 = x1;
        x1 = x2;
    }
    float vs = x1;

    size_t base = (size_t)b * K;
    fh[base + d]         = __float2half_rn(vl);
    fh[base + D + d]     = __float2half_rn(vm);
    fh[base + 2 * D + d] = __float2half_rn(vs);
}

// ---------------------------------------------------------------------------
// Kernel 2: W1 -> fp16 (each GEMM stream converts its own H-half)
// ---------------------------------------------------------------------------
__global__ __launch_bounds__(256) void w1_cvt_kernel(
    const float* __restrict__ W1,
    __half* __restrict__ wh)
{
    int i = (blockIdx.x * 256 + threadIdx.x) * 4;
    float4 v = *(const float4*)&W1[i];
    store_half4(&wh[i], v.x, v.y, v.z, v.w);
}

// ---------------------------------------------------------------------------
// Kernel 3: mma.sync fp16 GEMM + tanh + W2 reduction.
//   CTA 128x64, BK=64, 8 warps (4m x 2n), 2-stage cp.async, 48 KB smem.
//   One launch covers (BCH rows) x (512 cols of one H-half).
// ---------------------------------------------------------------------------
#define GT 256
#define OFF_A 0
#define OFF_B 16384
#define STAGE 24576
#define NSTAGE 2
#define GEMM_SMEM (NSTAGE * STAGE)   // 48 KB

__device__ __forceinline__ void load_stage(
    uint32_t sbase, const __half* aG, const __half* bG, int k0, int tid)
{
#pragma unroll
    for (int o = tid; o < 1024; o += GT) {
        int r = o >> 3, c = o & 7;
        uint32_t sw = sw128((uint32_t)(r * 128 + c * 16));
        size_t g = (size_t)r * K + k0 + c * 8;
        cpa16(sbase + OFF_A + sw, aG + g);
    }
#pragma unroll
    for (int o = tid; o < 512; o += GT) {
        int r = o >> 3, c = o & 7;
        uint32_t sw = sw128((uint32_t)(r * 128 + c * 16));
        size_t g = (size_t)r * K + k0 + c * 8;
        cpa16(sbase + OFF_B + sw, bG + g);
    }
}

__global__ void __launch_bounds__(GT, 2) gemm_mma_kernel(
    const __half* __restrict__ fh,    // chunk rows base
    const __half* __restrict__ wh,    // H-half base of fp16 W1
    const float* __restrict__ W2h,    // H-half base of W2
    float* __restrict__ out)          // chunk rows base
{
    extern __shared__ char smem[];
    const uint32_t sb = smem_u32(smem);
    const int tid  = threadIdx.x;
    const int wid  = tid >> 5;
    const int lane = tid & 31;
    const int wmw  = wid & 3;    // m rows wmw*32
    const int wn   = wid >> 2;   // n cols wn*32
    const int m0   = blockIdx.x * 128;
    const int n0   = blockIdx.y * 64;   // within this H-half (0..511)

    const __half* aG = fh + (size_t)m0 * K;
    const __half* bG = wh + (size_t)n0 * K;

    float acc[2][4][4];
#pragma unroll
    for (int mt = 0; mt < 2; ++mt)
#pragma unroll
        for (int nt = 0; nt < 4; ++nt)
#pragma unroll
            for (int e = 0; e < 4; ++e) acc[mt][nt][e] = 0.f;

    const int aRow = (lane & 15);
    const int aKch = (lane >> 4);
    const int bRow = ((lane >> 4) << 3) + (lane & 7);
    const int bKch = (lane >> 3) & 1;

    load_stage(sb,         aG, bG, 0,  tid);
    asm volatile("cp.async.commit_group;" ::: "memory");
    load_stage(sb + STAGE, aG, bG, 64, tid);
    asm volatile("cp.async.commit_group;" ::: "memory");

    for (int c = 0; c < 24; ++c) {
        if (c < 23) asm volatile("cp.async.wait_group 1;" ::: "memory");
        else        asm volatile("cp.async.wait_group 0;" ::: "memory");
        __syncthreads();

        const uint32_t sbase = sb + (c & 1) * STAGE;

#pragma unroll
        for (int ks = 0; ks < 4; ++ks) {
            uint32_t ah[2][4], bh[2][4];
#pragma unroll
            for (int mt = 0; mt < 2; ++mt) {
                uint32_t off = (uint32_t)((wmw * 32 + mt * 16 + aRow) * 128
                                          + ks * 32 + aKch * 16);
                ldsm4(ah[mt], sbase + OFF_A + sw128(off));
            }
#pragma unroll
            for (int g = 0; g < 2; ++g) {
                uint32_t off = (uint32_t)((wn * 32 + g * 16 + bRow) * 128
                                          + ks * 32 + bKch * 16);
                ldsm4(bh[g], sbase + OFF_B + sw128(off));
            }
#pragma unroll
            for (int mt = 0; mt < 2; ++mt) {
#pragma unroll
                for (int nt = 0; nt < 4; ++nt) {
                    const uint32_t* bp = &bh[nt >> 1][(nt & 1) * 2];
                    mma16816(acc[mt][nt], ah[mt], bp);
                }
            }
        }

        __syncthreads();
        if (c + 2 < 24) {
            load_stage(sbase, aG, bG, (c + 2) * 64, tid);
            asm volatile("cp.async.commit_group;" ::: "memory");
        }
    }

    // Epilogue: tanh + W2 dot, quad reduce, atomicAdd per row.
    float w2v[4][2];
#pragma unroll
    for (int nt = 0; nt < 4; ++nt) {
        int col = n0 + wn * 32 + nt * 8 + 2 * (lane & 3);
        w2v[nt][0] = W2h[col];
        w2v[nt][1] = W2h[col + 1];
    }

#pragma unroll
    for (int mt = 0; mt < 2; ++mt) {
        float p0 = 0.f, p1 = 0.f;
#pragma unroll
        for (int nt = 0; nt < 4; ++nt) {
            p0 += tanhf(acc[mt][nt][0]) * w2v[nt][0]
                + tanhf(acc[mt][nt][1]) * w2v[nt][1];
            p1 += tanhf(acc[mt][nt][2]) * w2v[nt][0]
                + tanhf(acc[mt][nt][3]) * w2v[nt][1];
        }
        p0 += __shfl_xor_sync(0xFFFFFFFFu, p0, 1);
        p0 += __shfl_xor_sync(0xFFFFFFFFu, p0, 2);
        p1 += __shfl_xor_sync(0xFFFFFFFFu, p1, 1);
        p1 += __shfl_xor_sync(0xFFFFFFFFu, p1, 2);
        if ((lane & 3) == 0) {
            int r = m0 + wmw * 32 + mt * 16 + (lane >> 2);
            atomicAdd(&out[r], p0);
            atomicAdd(&out[r + 8], p1);
        }
    }
}

// ---------------------------------------------------------------------------
// Launch: 3-stream fork-join. s0: feature chunks. s1/s2: GEMM chunks over
// the two H-halves in parallel (each 128 CTAs -> GEMM co-runs with features,
// as R8 demonstrated for minority-SM GEMM batches).
// ---------------------------------------------------------------------------
extern "C" void kernel_launch(void* const* d_in, const int* in_sizes, int n_in,
                              void* d_out, int out_size)
{
    const float* emb    = (const float*)d_in[0];  // [8192, 30, 512]
    const float* w_long = (const float*)d_in[1];  // [3]
    const float* w_mid  = (const float*)d_in[2];  // [3]
    const float* W1     = (const float*)d_in[3];  // [1024, 1536]
    const float* W2     = (const float*)d_in[4];  // [1, 1024]
    float* out = (float*)d_out;                   // [8192]

    __half *fh, *wh;
    cudaGetSymbolAddress((void**)&fh, g_fh);
    cudaGetSymbolAddress((void**)&wh, g_wh);

    // One-time host resources (not device memory; captured work identical per call)
    static cudaStream_t s1 = nullptr, s2 = nullptr;
    static cudaEvent_t e_fork, e_join1, e_join2;
    static cudaEvent_t e_feat[NCHUNK];
    if (!s1) {
        cudaStreamCreateWithFlags(&s1, cudaStreamNonBlocking);
        cudaStreamCreateWithFlags(&s2, cudaStreamNonBlocking);
        cudaEventCreateWithFlags(&e_fork,  cudaEventDisableTiming);
        cudaEventCreateWithFlags(&e_join1, cudaEventDisableTiming);
        cudaEventCreateWithFlags(&e_join2, cudaEventDisableTiming);
        for (int c = 0; c < NCHUNK; ++c)
            cudaEventCreateWithFlags(&e_feat[c], cudaEventDisableTiming);
    }

    static bool smem_set = false;
    if (!smem_set) {
        cudaFuncSetAttribute(gemm_mma_kernel,
                             cudaFuncAttributeMaxDynamicSharedMemorySize, GEMM_SMEM);
        smem_set = true;
    }

    cudaStream_t s0 = 0;   // capture-origin stream

    cudaMemsetAsync(out, 0, (size_t)Bsz * sizeof(float), s0);
    cudaEventRecord(e_fork, s0);
    cudaStreamWaitEvent(s1, e_fork, 0);
    cudaStreamWaitEvent(s2, e_fork, 0);

    // Each GEMM stream converts its own H-half of W1 (independent of features).
    {
        int elems_half = (H / 2) * K;              // 786432
        int blocks = (elems_half / 4) / 256;       // 768
        w1_cvt_kernel<<<blocks, 256, 0, s1>>>(W1, wh);
        w1_cvt_kernel<<<blocks, 256, 0, s2>>>(W1 + elems_half, wh + elems_half);
    }

    const int HHALF = H / 2;   // 512

    for (int c = 0; c < NCHUNK; ++c) {
        const size_t row0 = (size_t)c * BCH;
        feature_kernel<<<(BCH * D) / 256, 256, 0, s0>>>(
            emb + row0 * (S * D), w_long, w_mid, fh + row0 * K);
        cudaEventRecord(e_feat[c], s0);

        cudaStreamWaitEvent(s1, e_feat[c], 0);
        cudaStreamWaitEvent(s2, e_feat[c], 0);

        dim3 grid(BCH / 128, HHALF / 64);   // (16, 8) = 128 CTAs per stream
        gemm_mma_kernel<<<grid, GT, GEMM_SMEM, s1>>>(
            fh + row0 * K, wh, W2, out + row0);
        gemm_mma_kernel<<<grid, GT, GEMM_SMEM, s2>>>(
            fh + row0 * K, wh + (size_t)HHALF * K, W2 + HHALF, out + row0);
    }

    cudaEventRecord(e_join1, s1);
    cudaEventRecord(e_join2, s2);
    cudaStreamWaitEvent(s0, e_join1, 0);
    cudaStreamWaitEvent(s0, e_join2, 0);
}